// round 16
// baseline (speedup 1.0000x reference)
#include <cuda_runtime.h>
#include <math.h>

#define BSZ   512
#define SEQ   100
#define DIM   16
#define NH    36
#define ECOLS 1764        // 48*36 (E) + 36 (c)
#define COMB  176
#define NBLK  148
#define NTHR  256

// -------- scratch (__device__ globals: allocation-free) --------
__device__ __align__(16) float g_Ec[BSZ * ECOLS];      // [(i*9+kq)*2048 + b*4 + c]
__device__ __align__(16) float g_h[SEQ * NH * BSZ];    // [(s*36+k)*512 + b] (kept s only)
__device__ __align__(16) float g_coef[SEQ * BSZ];      // [s][b]
__device__ __align__(16) float g_y1[200 * BSZ];        // [f][b]
__device__ __align__(16) float g_y2[80 * BSZ];         // [f][b]
__device__ int g_skeep[SEQ];                            // overwritten each launch
__device__ unsigned long long g_s1sum[200];             // scaled int sums (zeroed pre-bar1)
__device__ unsigned long long g_s1sq[200];
__device__ unsigned g_cnt;                              // barrier (self-resetting)
__device__ volatile unsigned g_gen;                     // barrier generation (monotonic)

struct IdPtrs { const int* p[8]; };

union SMem {
    struct { float As[48][64]; } p2;                                     // 12 KB
    struct { float mu[NH]; float is[NH]; } p3;
    struct { float ys[4][201]; float mu[4]; float is[4]; float csh[4]; } p4;
    struct { float d1s[200][4]; float ys[80][5]; float mu[4]; float is[4]; } p6;
    struct { float mu2[80]; float is2[80]; float Wsh[160]; float Ash[80]; } p7;
};

__device__ __forceinline__ float sigm(float x) {
    return __fdividef(1.f, 1.f + __expf(-x));
}

// Atomic generation barrier (best measured: R9). Monotonic g_gen across
// replays; g_cnt self-resets. All NBLK blocks co-resident.
__device__ __forceinline__ void gbar() {
    __syncthreads();
    if (threadIdx.x == 0) {
        unsigned gen = g_gen;
        __threadfence();
        if (atomicAdd(&g_cnt, 1u) == NBLK - 1) {
            g_cnt = 0;
            __threadfence();
            g_gen = gen + 1;
        } else {
            while (g_gen == gen) {}
        }
    }
    __syncthreads();
}

__global__ __launch_bounds__(NTHR, 2) void din_fused(
        const float* __restrict__ table, IdPtrs ids,
        const int* __restrict__ vg, const int* __restrict__ vsh,
        const int* __restrict__ vc,
        const float* __restrict__ W1, const float* __restrict__ b1,
        const float* __restrict__ alpha_a, const float* __restrict__ wout,
        const float* __restrict__ bout,
        const float* __restrict__ Wm1, const float* __restrict__ bm1,
        const float* __restrict__ gl1, const float* __restrict__ bl1,
        const float* __restrict__ al1,
        const float* __restrict__ Wm2, const float* __restrict__ bm2,
        const float* __restrict__ gl2, const float* __restrict__ bl2,
        const float* __restrict__ al2,
        const float* __restrict__ Wo, const float* __restrict__ bo,
        float* __restrict__ out) {
    __shared__ SMem sm;
    __shared__ float xs[4][COMB];       // outside union: survives rare path
    __shared__ int skeepS[SEQ];
    int bid = blockIdx.x;
    int t = threadIdx.x;

    // ---------------- P0: profile gather + stats-accumulator zeroing ---------
    if (bid < 128) {
        int b0 = bid * 4;
        for (int p = t; p < 4 * 128; p += NTHR) {
            int bl = p >> 7, f = p & 127;
            xs[bl][f] = table[(size_t)ids.p[f >> 4][b0 + bl] * DIM + (f & 15)];
        }
        if (t < 4 * 48) { int bl = t / 48, i = t - bl * 48; xs[bl][128 + i] = 0.f; }
    }
    if (bid == 130 && t < 200) { g_s1sum[t] = 0ull; g_s1sq[t] = 0ull; }

    // ---------------- P1: per-s keep mask (overwrite; no reset needed) -------
    if (bid < SEQ) {
        int any = 0;
        for (int b = t; b < BSZ; b += NTHR) any |= (vg[b * SEQ + bid] == 0);
        int r = __syncthreads_or(any);
        if (t == 0) g_skeep[bid] = r;
    }

    // ---------------- P2: E GEMM (pre-barrier: independent of the mask) ------
    for (int tile = bid; tile < 448; tile += NBLK) {
        int cx = tile % 56, by = tile / 56;
        int b_base = by * 64;
        __syncthreads();
        for (int p = t; p < 48 * 64; p += NTHR) {
            int j = p >> 6, bl = p & 63;
            int which = j >> 4;
            int id = ids.p[5 + which][b_base + bl];
            sm.p2.As[j][bl] = table[(size_t)id * DIM + (j & 15)];
        }
        __syncthreads();
        int tx = t & 31, ty = t >> 5;
        int col = cx * 32 + tx;
        if (col < ECOLS) {
            int b0 = ty * 8;
            float acc[8];
#pragma unroll
            for (int r = 0; r < 8; r++) acc[r] = 0.f;
            int ii, kk;
            if (col < 1728) {
                ii = col / 36; kk = col - ii * 36;
                const float* wp = W1 + (size_t)(144 + ii * 48) * 36 + kk;
#pragma unroll 8
                for (int j = 0; j < 48; j++) {
                    float w = wp[j * 36];
                    float4 a0 = *(const float4*)&sm.p2.As[j][b0];
                    float4 a1 = *(const float4*)&sm.p2.As[j][b0 + 4];
                    acc[0] += w * a0.x; acc[1] += w * a0.y; acc[2] += w * a0.z; acc[3] += w * a0.w;
                    acc[4] += w * a1.x; acc[5] += w * a1.y; acc[6] += w * a1.z; acc[7] += w * a1.w;
                }
                float wcb = W1[(96 + ii) * 36 + kk] - W1[(48 + ii) * 36 + kk];
#pragma unroll
                for (int r = 0; r < 8; r++) acc[r] += wcb;
            } else {
                ii = 48; kk = col - 1728;
#pragma unroll 8
                for (int j = 0; j < 48; j++) {
                    float w = W1[j * 36 + kk] + W1[(48 + j) * 36 + kk];
                    float4 a0 = *(const float4*)&sm.p2.As[j][b0];
                    float4 a1 = *(const float4*)&sm.p2.As[j][b0 + 4];
                    acc[0] += w * a0.x; acc[1] += w * a0.y; acc[2] += w * a0.z; acc[3] += w * a0.w;
                    acc[4] += w * a1.x; acc[5] += w * a1.y; acc[6] += w * a1.z; acc[7] += w * a1.w;
                }
                float bb = b1[kk];
#pragma unroll
                for (int r = 0; r < 8; r++) acc[r] += bb;
            }
            int kq = kk >> 2, c = kk & 3;
            size_t base = (size_t)(ii * 9 + kq) * 2048 + c;
#pragma unroll
            for (int r = 0; r < 8; r++)
                g_Ec[base + (size_t)(b_base + b0 + r) * 4] = acc[r];
        }
    }
    gbar();                                                   // barrier 1

    int v0 = (t < SEQ) ? g_skeep[t] : 0;
    if (t < SEQ) skeepS[t] = v0;
    int anyAll = __syncthreads_or(v0);   // uniform across blocks

    // ============ rare path: activation unit (ONE extra barrier) =============
    if (anyAll) {
        // ---- P3 merged: one block per kept s. Compute h for ALL 512 b (two
        // passes), block-local stats (syncthreads orders own global writes),
        // then dice+score+mask -> coef. No grid barrier between h and stats.
        for (int s = bid; s < SEQ; s += NBLK) {
            if (!skeepS[s]) continue;
#pragma unroll 1
            for (int half = 0; half < 2; half++) {
                int b = half * 256 + t;
                int id0 = vg[b * SEQ + s];
                int id1 = vsh[b * SEQ + s];
                int id2 = vc[b * SEQ + s];
                float vs[48];
                {
                    const float4* r = (const float4*)(table + (size_t)id0 * DIM);
                    float4 a = r[0], bb = r[1], cc = r[2], dd = r[3];
                    vs[0]=a.x; vs[1]=a.y; vs[2]=a.z; vs[3]=a.w;
                    vs[4]=bb.x; vs[5]=bb.y; vs[6]=bb.z; vs[7]=bb.w;
                    vs[8]=cc.x; vs[9]=cc.y; vs[10]=cc.z; vs[11]=cc.w;
                    vs[12]=dd.x; vs[13]=dd.y; vs[14]=dd.z; vs[15]=dd.w;
                    r = (const float4*)(table + (size_t)id1 * DIM);
                    a = r[0]; bb = r[1]; cc = r[2]; dd = r[3];
                    vs[16]=a.x; vs[17]=a.y; vs[18]=a.z; vs[19]=a.w;
                    vs[20]=bb.x; vs[21]=bb.y; vs[22]=bb.z; vs[23]=bb.w;
                    vs[24]=cc.x; vs[25]=cc.y; vs[26]=cc.z; vs[27]=cc.w;
                    vs[28]=dd.x; vs[29]=dd.y; vs[30]=dd.z; vs[31]=dd.w;
                    r = (const float4*)(table + (size_t)id2 * DIM);
                    a = r[0]; bb = r[1]; cc = r[2]; dd = r[3];
                    vs[32]=a.x; vs[33]=a.y; vs[34]=a.z; vs[35]=a.w;
                    vs[36]=bb.x; vs[37]=bb.y; vs[38]=bb.z; vs[39]=bb.w;
                    vs[40]=cc.x; vs[41]=cc.y; vs[42]=cc.z; vs[43]=cc.w;
                    vs[44]=dd.x; vs[45]=dd.y; vs[46]=dd.z; vs[47]=dd.w;
                }
                const float4* E4 = (const float4*)g_Ec;
                float h[36];
#pragma unroll
                for (int kq = 0; kq < 9; kq++) {
                    float4 cv = E4[(size_t)(432 + kq) * 512 + b];
                    h[kq*4+0]=cv.x; h[kq*4+1]=cv.y; h[kq*4+2]=cv.z; h[kq*4+3]=cv.w;
                }
                for (int i = 0; i < 48; i++) {
                    float v = vs[i];
#pragma unroll
                    for (int kq = 0; kq < 9; kq++) {
                        float4 e = E4[(size_t)(i * 9 + kq) * 512 + b];
                        h[kq*4+0] += v * e.x; h[kq*4+1] += v * e.y;
                        h[kq*4+2] += v * e.z; h[kq*4+3] += v * e.w;
                    }
                }
#pragma unroll
                for (int k = 0; k < 36; k++)
                    g_h[(size_t)(s * NH + k) * BSZ + b] = h[k];
            }
            __syncthreads();   // orders this block's g_h writes for re-read

            // stats over all 512 b (rows of g_h written by THIS block)
            {
                int w = t >> 5, lane = t & 31;
                for (int k = w; k < NH; k += 8) {
                    const float4* row = (const float4*)(g_h + (size_t)(s * NH + k) * BSZ);
                    float smv = 0.f, sq = 0.f;
#pragma unroll
                    for (int i = 0; i < 4; i++) {
                        float4 v = row[lane + 32 * i];
                        smv += v.x + v.y + v.z + v.w;
                        sq += v.x * v.x + v.y * v.y + v.z * v.z + v.w * v.w;
                    }
#pragma unroll
                    for (int o = 16; o; o >>= 1) {
                        smv += __shfl_down_sync(0xffffffffu, smv, o);
                        sq  += __shfl_down_sync(0xffffffffu, sq, o);
                    }
                    if (lane == 0) {
                        float mu = smv * (1.f / 512.f);
                        float var = sq * (1.f / 512.f) - mu * mu;
                        sm.p3.mu[k] = mu; sm.p3.is[k] = rsqrtf(var + 1e-3f);
                    }
                }
            }
            __syncthreads();

            // dice + score + mask -> coef (both halves)
            {
                float bout0 = bout[0];
#pragma unroll 1
                for (int half = 0; half < 2; half++) {
                    int b = half * 256 + t;
                    float accv = 0.f;
#pragma unroll 4
                    for (int k = 0; k < NH; k++) {
                        float x = g_h[(size_t)(s * NH + k) * BSZ + b];
                        float xn = (x - sm.p3.mu[k]) * sm.p3.is[k];
                        float p = sigm(xn);
                        accv += wout[k] * x * (p + alpha_a[k] * (1.f - p));
                    }
                    int vgv = vg[b * SEQ + s];
                    g_coef[s * BSZ + b] = (vgv == 0) ? (accv + bout0) : 0.f;
                }
            }
            __syncthreads();
        }
        gbar();                                               // barrier 2 (rare)

        // ---- x_inter accumulation into xs ----
        if (bid < 128) {
            int b0 = bid * 4;
            for (int s = 0; s < SEQ; s++) {
                if (!skeepS[s]) continue;
                if (t < 4) sm.p4.csh[t] = g_coef[s * BSZ + b0 + t];
                __syncthreads();
                if (t < 4 * 48) {
                    int bl = t / 48, i = t - bl * 48;
                    float c = sm.p4.csh[bl];
                    if (c != 0.f) {
                        int which = i >> 4;
                        int id = (which == 0) ? vg[(b0 + bl) * SEQ + s]
                               : (which == 1) ? vsh[(b0 + bl) * SEQ + s]
                                              : vc[(b0 + bl) * SEQ + s];
                        xs[bl][128 + i] += c * table[(size_t)id * DIM + (i & 15)];
                    }
                }
                __syncthreads();
            }
        }
    }

    // ---------------- P4: MLP1 + LN -> y1T + integer stats atomics -----------
    if (bid < 128) {
        int b0 = bid * 4;
        if (t < 200) {
            float bb = bm1[t];
            float acc0 = bb, acc1 = bb, acc2 = bb, acc3 = bb;
            const float* wp = Wm1 + t;
#pragma unroll 8
            for (int j = 0; j < COMB; j++) {
                float w = wp[j * 200];
                acc0 += w * xs[0][j];
                acc1 += w * xs[1][j];
                acc2 += w * xs[2][j];
                acc3 += w * xs[3][j];
            }
            sm.p4.ys[0][t] = acc0; sm.p4.ys[1][t] = acc1;
            sm.p4.ys[2][t] = acc2; sm.p4.ys[3][t] = acc3;
        }
        __syncthreads();
        if (t < 128) {
            int w = t >> 5, lane = t & 31;
            float smv = 0.f, sq = 0.f;
            for (int c = lane; c < 200; c += 32) { float v = sm.p4.ys[w][c]; smv += v; sq += v * v; }
#pragma unroll
            for (int o = 16; o; o >>= 1) {
                smv += __shfl_down_sync(0xffffffffu, smv, o);
                sq  += __shfl_down_sync(0xffffffffu, sq, o);
            }
            if (lane == 0) {
                float mu = smv * (1.f / 200.f);
                float var = sq * (1.f / 200.f) - mu * mu;
                sm.p4.mu[w] = mu; sm.p4.is[w] = rsqrtf(var + 1e-3f);
            }
        }
        __syncthreads();
        if (t < 200) {
            float gg = gl1[t], be = bl1[t];
            long long s24 = 0, s20 = 0;
#pragma unroll
            for (int r = 0; r < 4; r++) {
                float v = (sm.p4.ys[r][t] - sm.p4.mu[r]) * sm.p4.is[r] * gg + be;
                g_y1[(size_t)t * BSZ + b0 + r] = v;
                s24 += llrintf(v * 16777216.f);            // 2^24 scale
                long long a20 = llrintf(v * 1048576.f);    // 2^20 scale
                s20 += a20 * a20;                          // v^2 * 2^40
            }
            atomicAdd(&g_s1sum[t], (unsigned long long)s24);
            atomicAdd(&g_s1sq[t],  (unsigned long long)s20);
        }
    }
    gbar();                                                   // barrier 3

    // ---------------- P6: stats from int sums + dice + MLP2 + LN -> y2T ------
    if (bid < 128) {
        int b0 = bid * 4;
        if (t < 200) {
            long long s = (long long)g_s1sum[t];
            long long q = (long long)g_s1sq[t];
            float mu = (float)s * (1.f / (512.f * 16777216.f));
            float ex2 = (float)q * (1.f / (512.f * 1099511627776.f));   // /2^40
            float is = rsqrtf(ex2 - mu * mu + 1e-3f);
            float a = al1[t];
            float4 v = *(const float4*)(g_y1 + (size_t)t * BSZ + b0);
            float p;
            p = sigm((v.x - mu) * is); sm.p6.d1s[t][0] = v.x * (p + a * (1.f - p));
            p = sigm((v.y - mu) * is); sm.p6.d1s[t][1] = v.y * (p + a * (1.f - p));
            p = sigm((v.z - mu) * is); sm.p6.d1s[t][2] = v.z * (p + a * (1.f - p));
            p = sigm((v.w - mu) * is); sm.p6.d1s[t][3] = v.w * (p + a * (1.f - p));
        }
        __syncthreads();

        if (t < 80) {
            float bb = bm2[t];
            float acc0 = bb, acc1 = bb, acc2 = bb, acc3 = bb;
            const float* wp = Wm2 + t;
#pragma unroll 8
            for (int j = 0; j < 200; j++) {
                float w = wp[j * 80];
                acc0 += w * sm.p6.d1s[j][0];
                acc1 += w * sm.p6.d1s[j][1];
                acc2 += w * sm.p6.d1s[j][2];
                acc3 += w * sm.p6.d1s[j][3];
            }
            sm.p6.ys[t][0] = acc0; sm.p6.ys[t][1] = acc1;
            sm.p6.ys[t][2] = acc2; sm.p6.ys[t][3] = acc3;
        }
        __syncthreads();
        if (t < 128) {
            int w = t >> 5, lane = t & 31;
            float smv = 0.f, sq = 0.f;
            for (int c = lane; c < 80; c += 32) { float v = sm.p6.ys[c][w]; smv += v; sq += v * v; }
#pragma unroll
            for (int o = 16; o; o >>= 1) {
                smv += __shfl_down_sync(0xffffffffu, smv, o);
                sq  += __shfl_down_sync(0xffffffffu, sq, o);
            }
            if (lane == 0) {
                float mu = smv * (1.f / 80.f);
                float var = sq * (1.f / 80.f) - mu * mu;
                sm.p6.mu[w] = mu; sm.p6.is[w] = rsqrtf(var + 1e-3f);
            }
        }
        __syncthreads();
        if (t < 80) {
            float gg = gl2[t], be = bl2[t];
#pragma unroll
            for (int r = 0; r < 4; r++)
                g_y2[(size_t)t * BSZ + b0 + r] =
                    (sm.p6.ys[t][r] - sm.p6.mu[r]) * sm.p6.is[r] * gg + be;
        }
    }
    gbar();                                                   // barrier 4

    // ---------------- P7: stats2 + dice + out GEMM + softmax ----------------
    if (bid < 32) {
        int w = t >> 5, lane = t & 31;
        int b0 = bid * 16;
        if (t < 160) sm.p7.Wsh[t] = Wo[t];
        if (t < 80) sm.p7.Ash[t] = al2[t];
        for (int r = 0; r < 10; r++) {
            int f = w * 10 + r;
            const float4* row = (const float4*)(g_y2 + (size_t)f * BSZ);
            float smv = 0.f, sq = 0.f;
#pragma unroll
            for (int i = 0; i < 4; i++) {
                float4 v = row[lane + 32 * i];
                smv += v.x + v.y + v.z + v.w;
                sq += v.x * v.x + v.y * v.y + v.z * v.z + v.w * v.w;
            }
#pragma unroll
            for (int o = 16; o; o >>= 1) {
                smv += __shfl_down_sync(0xffffffffu, smv, o);
                sq  += __shfl_down_sync(0xffffffffu, sq, o);
            }
            if (lane == 0) {
                float mu = smv * (1.f / 512.f);
                float var = sq * (1.f / 512.f) - mu * mu;
                sm.p7.mu2[f] = mu; sm.p7.is2[f] = rsqrtf(var + 1e-3f);
            }
        }
        __syncthreads();
        float bo0 = bo[0], bo1 = bo[1];
#pragma unroll
        for (int rep = 0; rep < 2; rep++) {
            int b = b0 + w + rep * 8;
            float a0 = 0.f, a1 = 0.f;
            for (int f = lane; f < 80; f += 32) {
                float v = g_y2[(size_t)f * BSZ + b];
                float xn = (v - sm.p7.mu2[f]) * sm.p7.is2[f];
                float p = sigm(xn);
                float h = v * (p + sm.p7.Ash[f] * (1.f - p));
                a0 += h * sm.p7.Wsh[2 * f];
                a1 += h * sm.p7.Wsh[2 * f + 1];
            }
#pragma unroll
            for (int o = 16; o; o >>= 1) {
                a0 += __shfl_down_sync(0xffffffffu, a0, o);
                a1 += __shfl_down_sync(0xffffffffu, a1, o);
            }
            if (lane == 0) {
                a0 += bo0; a1 += bo1;
                float m = fmaxf(a0, a1);
                float e0 = __expf(a0 - m), e1 = __expf(a1 - m);
                float inv = __fdividef(1.f, e0 + e1);
                out[b * 2] = e0 * inv;
                out[b * 2 + 1] = e1 * inv;
            }
        }
    }
}

// ============================================================================
extern "C" void kernel_launch(void* const* d_in, const int* in_sizes, int n_in,
                              void* d_out, int out_size) {
    (void)in_sizes; (void)n_in; (void)out_size;
    const int* uid  = (const int*)d_in[0];
    const int* ut1  = (const int*)d_in[1];
    const int* ut2  = (const int*)d_in[2];
    const int* ut3  = (const int*)d_in[3];
    const int* ut4  = (const int*)d_in[4];
    const int* ig   = (const int*)d_in[5];
    const int* ish  = (const int*)d_in[6];
    const int* ic   = (const int*)d_in[7];
    const int* vg   = (const int*)d_in[8];
    const int* vsh  = (const int*)d_in[9];
    const int* vc   = (const int*)d_in[10];
    const float* table     = (const float*)d_in[11];
    const float* W_act1    = (const float*)d_in[12];
    const float* b_act1    = (const float*)d_in[13];
    const float* alpha_act = (const float*)d_in[14];
    const float* W_act_out = (const float*)d_in[15];
    const float* b_act_out = (const float*)d_in[16];
    const float* W_mlp1    = (const float*)d_in[17];
    const float* b_mlp1    = (const float*)d_in[18];
    const float* g_ln1     = (const float*)d_in[19];
    const float* beta_ln1  = (const float*)d_in[20];
    const float* alpha_m1  = (const float*)d_in[21];
    const float* W_mlp2    = (const float*)d_in[22];
    const float* b_mlp2    = (const float*)d_in[23];
    const float* g_ln2     = (const float*)d_in[24];
    const float* beta_ln2  = (const float*)d_in[25];
    const float* alpha_m2  = (const float*)d_in[26];
    const float* W_out     = (const float*)d_in[27];
    const float* b_out     = (const float*)d_in[28];
    float* out = (float*)d_out;

    IdPtrs ids;
    ids.p[0] = uid; ids.p[1] = ut1; ids.p[2] = ut2; ids.p[3] = ut3;
    ids.p[4] = ut4; ids.p[5] = ig;  ids.p[6] = ish; ids.p[7] = ic;

    din_fused<<<NBLK, NTHR>>>(table, ids, vg, vsh, vc,
                              W_act1, b_act1, alpha_act, W_act_out, b_act_out,
                              W_mlp1, b_mlp1, g_ln1, beta_ln1, alpha_m1,
                              W_mlp2, b_mlp2, g_ln2, beta_ln2, alpha_m2,
                              W_out, b_out, out);
}

// round 17
// speedup vs baseline: 1.5723x; 1.5723x over previous
#include <cuda_runtime.h>
#include <math.h>

#define BSZ   512
#define SEQ   100
#define DIM   16
#define NH    36
#define ECOLS 1764        // 48*36 (E) + 36 (c)
#define COMB  176
#define NBLK  148
#define NTHR  256

// -------- scratch (__device__ globals: allocation-free) --------
__device__ __align__(16) float g_Ec[BSZ * ECOLS];      // [(i*9+kq)*2048 + b*4 + c]
__device__ __align__(16) float g_h[SEQ * NH * BSZ];    // [(s*36+k)*512 + b] (kept s only)
__device__ __align__(16) float g_coef[SEQ * BSZ];      // [s][b]
__device__ __align__(16) float g_y1[200 * BSZ];        // [f][b]
__device__ __align__(16) float g_y2[80 * BSZ];         // [f][b]
__device__ int g_skeep[SEQ];                            // overwritten each launch
__device__ unsigned long long g_s1sum[200];             // scaled int sums (zeroed pre-bar1)
__device__ unsigned long long g_s1sq[200];
__device__ unsigned g_cnt;                              // barrier (self-resetting)
__device__ volatile unsigned g_gen;                     // barrier generation (monotonic)

struct IdPtrs { const int* p[8]; };

union SMem {
    struct { float As[48][64]; } p2;                                     // 12 KB
    struct { float mu[NH]; float is[NH]; } p3;
    struct { float ys[4][201]; float mu[4]; float is[4]; float csh[4]; } p4;
    struct { float d1s[200][4]; float ys[80][5]; float mu[4]; float is[4]; } p6;
    struct { float mu2[80]; float is2[80]; float Wsh[160]; float Ash[80]; } p7;
};

__device__ __forceinline__ float sigm(float x) {
    return __fdividef(1.f, 1.f + __expf(-x));
}

// Atomic generation barrier (best measured: R9). Monotonic g_gen across
// replays; g_cnt self-resets. All NBLK blocks co-resident.
__device__ __forceinline__ void gbar() {
    __syncthreads();
    if (threadIdx.x == 0) {
        unsigned gen = g_gen;
        __threadfence();
        if (atomicAdd(&g_cnt, 1u) == NBLK - 1) {
            g_cnt = 0;
            __threadfence();
            g_gen = gen + 1;
        } else {
            while (g_gen == gen) {}
        }
    }
    __syncthreads();
}

__global__ __launch_bounds__(NTHR, 2) void din_fused(
        const float* __restrict__ table, IdPtrs ids,
        const int* __restrict__ vg, const int* __restrict__ vsh,
        const int* __restrict__ vc,
        const float* __restrict__ W1, const float* __restrict__ b1,
        const float* __restrict__ alpha_a, const float* __restrict__ wout,
        const float* __restrict__ bout,
        const float* __restrict__ Wm1, const float* __restrict__ bm1,
        const float* __restrict__ gl1, const float* __restrict__ bl1,
        const float* __restrict__ al1,
        const float* __restrict__ Wm2, const float* __restrict__ bm2,
        const float* __restrict__ gl2, const float* __restrict__ bl2,
        const float* __restrict__ al2,
        const float* __restrict__ Wo, const float* __restrict__ bo,
        float* __restrict__ out) {
    __shared__ SMem sm;
    __shared__ float xs[4][COMB];       // outside union: survives rare path
    __shared__ int skeepS[SEQ];
    int bid = blockIdx.x;
    int t = threadIdx.x;

    // ---------------- P0: profile gather + stats-accumulator zeroing ---------
    if (bid < 128) {
        int b0 = bid * 4;
        for (int p = t; p < 4 * 128; p += NTHR) {
            int bl = p >> 7, f = p & 127;
            xs[bl][f] = table[(size_t)ids.p[f >> 4][b0 + bl] * DIM + (f & 15)];
        }
        if (t < 4 * 48) { int bl = t / 48, i = t - bl * 48; xs[bl][128 + i] = 0.f; }
    }
    if (bid == 130 && t < 200) { g_s1sum[t] = 0ull; g_s1sq[t] = 0ull; }

    // ---------------- P1: per-s keep mask (overwrite; no reset needed) -------
    if (bid < SEQ) {
        int any = 0;
        for (int b = t; b < BSZ; b += NTHR) any |= (vg[b * SEQ + bid] == 0);
        int r = __syncthreads_or(any);
        if (t == 0) g_skeep[bid] = r;
    }
    gbar();                                                   // barrier 1

    int v0 = (t < SEQ) ? g_skeep[t] : 0;
    if (t < SEQ) skeepS[t] = v0;
    int anyAll = __syncthreads_or(v0);   // uniform across blocks

    // ============ rare path: activation unit (3 extra barriers, uniform) =====
    if (anyAll) {
        // ---- P2: E GEMM ----
        for (int tile = bid; tile < 448; tile += NBLK) {
            int cx = tile % 56, by = tile / 56;
            int b_base = by * 64;
            for (int p = t; p < 48 * 64; p += NTHR) {
                int j = p >> 6, bl = p & 63;
                int which = j >> 4;
                int id = ids.p[5 + which][b_base + bl];
                sm.p2.As[j][bl] = table[(size_t)id * DIM + (j & 15)];
            }
            __syncthreads();
            int tx = t & 31, ty = t >> 5;
            int col = cx * 32 + tx;
            if (col < ECOLS) {
                int b0 = ty * 8;
                float acc[8];
#pragma unroll
                for (int r = 0; r < 8; r++) acc[r] = 0.f;
                int ii, kk;
                if (col < 1728) {
                    ii = col / 36; kk = col - ii * 36;
                    const float* wp = W1 + (size_t)(144 + ii * 48) * 36 + kk;
#pragma unroll 8
                    for (int j = 0; j < 48; j++) {
                        float w = wp[j * 36];
                        float4 a0 = *(const float4*)&sm.p2.As[j][b0];
                        float4 a1 = *(const float4*)&sm.p2.As[j][b0 + 4];
                        acc[0] += w * a0.x; acc[1] += w * a0.y; acc[2] += w * a0.z; acc[3] += w * a0.w;
                        acc[4] += w * a1.x; acc[5] += w * a1.y; acc[6] += w * a1.z; acc[7] += w * a1.w;
                    }
                    float wcb = W1[(96 + ii) * 36 + kk] - W1[(48 + ii) * 36 + kk];
#pragma unroll
                    for (int r = 0; r < 8; r++) acc[r] += wcb;
                } else {
                    ii = 48; kk = col - 1728;
#pragma unroll 8
                    for (int j = 0; j < 48; j++) {
                        float w = W1[j * 36 + kk] + W1[(48 + j) * 36 + kk];
                        float4 a0 = *(const float4*)&sm.p2.As[j][b0];
                        float4 a1 = *(const float4*)&sm.p2.As[j][b0 + 4];
                        acc[0] += w * a0.x; acc[1] += w * a0.y; acc[2] += w * a0.z; acc[3] += w * a0.w;
                        acc[4] += w * a1.x; acc[5] += w * a1.y; acc[6] += w * a1.z; acc[7] += w * a1.w;
                    }
                    float bb = b1[kk];
#pragma unroll
                    for (int r = 0; r < 8; r++) acc[r] += bb;
                }
                int kq = kk >> 2, c = kk & 3;
                size_t base = (size_t)(ii * 9 + kq) * 2048 + c;
#pragma unroll
                for (int r = 0; r < 8; r++)
                    g_Ec[base + (size_t)(b_base + b0 + r) * 4] = acc[r];
            }
            __syncthreads();
        }
        gbar();

        // ---- P3a: h_pre for kept s, split over (s, half, kq-group) ----
        // 600 units: s = u/6, half = u&1, kqg = (u%6)>>1 in {0,1,2}.
        // Each block computes 12 k (3 kq groups of 4) for 256 b -> E read/block
        // drops 3x; for nk=1 six blocks stream E in parallel instead of two.
        for (int u = bid; u < 600; u += NBLK) {
            int s = u / 6;
            if (!skeepS[s]) continue;
            int r6 = u - s * 6;
            int half = r6 & 1;
            int kqg = r6 >> 1;            // 0,1,2 -> kq base kqg*3
            int b = half * 256 + t;
            int id0 = vg[b * SEQ + s];
            int id1 = vsh[b * SEQ + s];
            int id2 = vc[b * SEQ + s];
            float vs[48];
            {
                const float4* r = (const float4*)(table + (size_t)id0 * DIM);
                float4 a = r[0], bb = r[1], cc = r[2], dd = r[3];
                vs[0]=a.x; vs[1]=a.y; vs[2]=a.z; vs[3]=a.w;
                vs[4]=bb.x; vs[5]=bb.y; vs[6]=bb.z; vs[7]=bb.w;
                vs[8]=cc.x; vs[9]=cc.y; vs[10]=cc.z; vs[11]=cc.w;
                vs[12]=dd.x; vs[13]=dd.y; vs[14]=dd.z; vs[15]=dd.w;
                r = (const float4*)(table + (size_t)id1 * DIM);
                a = r[0]; bb = r[1]; cc = r[2]; dd = r[3];
                vs[16]=a.x; vs[17]=a.y; vs[18]=a.z; vs[19]=a.w;
                vs[20]=bb.x; vs[21]=bb.y; vs[22]=bb.z; vs[23]=bb.w;
                vs[24]=cc.x; vs[25]=cc.y; vs[26]=cc.z; vs[27]=cc.w;
                vs[28]=dd.x; vs[29]=dd.y; vs[30]=dd.z; vs[31]=dd.w;
                r = (const float4*)(table + (size_t)id2 * DIM);
                a = r[0]; bb = r[1]; cc = r[2]; dd = r[3];
                vs[32]=a.x; vs[33]=a.y; vs[34]=a.z; vs[35]=a.w;
                vs[36]=bb.x; vs[37]=bb.y; vs[38]=bb.z; vs[39]=bb.w;
                vs[40]=cc.x; vs[41]=cc.y; vs[42]=cc.z; vs[43]=cc.w;
                vs[44]=dd.x; vs[45]=dd.y; vs[46]=dd.z; vs[47]=dd.w;
            }
            const float4* E4 = (const float4*)g_Ec;
            float h[12];
#pragma unroll
            for (int kqi = 0; kqi < 3; kqi++) {
                int kq = kqg * 3 + kqi;
                float4 cv = E4[(size_t)(432 + kq) * 512 + b];
                h[kqi*4+0]=cv.x; h[kqi*4+1]=cv.y; h[kqi*4+2]=cv.z; h[kqi*4+3]=cv.w;
            }
            for (int i = 0; i < 48; i++) {
                float v = vs[i];
#pragma unroll
                for (int kqi = 0; kqi < 3; kqi++) {
                    int kq = kqg * 3 + kqi;
                    float4 e = E4[(size_t)(i * 9 + kq) * 512 + b];
                    h[kqi*4+0] += v * e.x; h[kqi*4+1] += v * e.y;
                    h[kqi*4+2] += v * e.z; h[kqi*4+3] += v * e.w;
                }
            }
#pragma unroll
            for (int kqi = 0; kqi < 3; kqi++) {
                int kbase = s * NH + (kqg * 3 + kqi) * 4;
                g_h[(size_t)(kbase + 0) * BSZ + b] = h[kqi*4+0];
                g_h[(size_t)(kbase + 1) * BSZ + b] = h[kqi*4+1];
                g_h[(size_t)(kbase + 2) * BSZ + b] = h[kqi*4+2];
                g_h[(size_t)(kbase + 3) * BSZ + b] = h[kqi*4+3];
            }
        }
        gbar();

        // ---- P3b: stats + dice + score + mask -> coef ----
        {
            float bout0 = bout[0];
            for (int it = bid; it < 200; it += NBLK) {
                int s = it >> 1, half = it & 1;
                if (!skeepS[s]) continue;
                int w = t >> 5, lane = t & 31;
                for (int k = w; k < NH; k += 8) {
                    const float4* row = (const float4*)(g_h + (size_t)(s * NH + k) * BSZ);
                    float smv = 0.f, sq = 0.f;
#pragma unroll
                    for (int i = 0; i < 4; i++) {
                        float4 v = row[lane + 32 * i];
                        smv += v.x + v.y + v.z + v.w;
                        sq += v.x * v.x + v.y * v.y + v.z * v.z + v.w * v.w;
                    }
#pragma unroll
                    for (int o = 16; o; o >>= 1) {
                        smv += __shfl_down_sync(0xffffffffu, smv, o);
                        sq  += __shfl_down_sync(0xffffffffu, sq, o);
                    }
                    if (lane == 0) {
                        float mu = smv * (1.f / 512.f);
                        float var = sq * (1.f / 512.f) - mu * mu;
                        sm.p3.mu[k] = mu; sm.p3.is[k] = rsqrtf(var + 1e-3f);
                    }
                }
                __syncthreads();
                int b = half * 256 + t;
                float accv = 0.f;
#pragma unroll 4
                for (int k = 0; k < NH; k++) {
                    float x = g_h[(size_t)(s * NH + k) * BSZ + b];
                    float xn = (x - sm.p3.mu[k]) * sm.p3.is[k];
                    float p = sigm(xn);
                    accv += wout[k] * x * (p + alpha_a[k] * (1.f - p));
                }
                int vgv = vg[b * SEQ + s];
                g_coef[s * BSZ + b] = (vgv == 0) ? (accv + bout0) : 0.f;
                __syncthreads();
            }
        }
        gbar();

        // ---- x_inter accumulation into xs ----
        if (bid < 128) {
            int b0 = bid * 4;
            for (int s = 0; s < SEQ; s++) {
                if (!skeepS[s]) continue;
                if (t < 4) sm.p4.csh[t] = g_coef[s * BSZ + b0 + t];
                __syncthreads();
                if (t < 4 * 48) {
                    int bl = t / 48, i = t - bl * 48;
                    float c = sm.p4.csh[bl];
                    if (c != 0.f) {
                        int which = i >> 4;
                        int id = (which == 0) ? vg[(b0 + bl) * SEQ + s]
                               : (which == 1) ? vsh[(b0 + bl) * SEQ + s]
                                              : vc[(b0 + bl) * SEQ + s];
                        xs[bl][128 + i] += c * table[(size_t)id * DIM + (i & 15)];
                    }
                }
                __syncthreads();
            }
        }
    }

    // ---------------- P4: MLP1 + LN -> y1T + integer stats atomics -----------
    if (bid < 128) {
        int b0 = bid * 4;
        if (t < 200) {
            float bb = bm1[t];
            float acc0 = bb, acc1 = bb, acc2 = bb, acc3 = bb;
            const float* wp = Wm1 + t;
#pragma unroll 8
            for (int j = 0; j < COMB; j++) {
                float w = wp[j * 200];
                acc0 += w * xs[0][j];
                acc1 += w * xs[1][j];
                acc2 += w * xs[2][j];
                acc3 += w * xs[3][j];
            }
            sm.p4.ys[0][t] = acc0; sm.p4.ys[1][t] = acc1;
            sm.p4.ys[2][t] = acc2; sm.p4.ys[3][t] = acc3;
        }
        __syncthreads();
        if (t < 128) {
            int w = t >> 5, lane = t & 31;
            float smv = 0.f, sq = 0.f;
            for (int c = lane; c < 200; c += 32) { float v = sm.p4.ys[w][c]; smv += v; sq += v * v; }
#pragma unroll
            for (int o = 16; o; o >>= 1) {
                smv += __shfl_down_sync(0xffffffffu, smv, o);
                sq  += __shfl_down_sync(0xffffffffu, sq, o);
            }
            if (lane == 0) {
                float mu = smv * (1.f / 200.f);
                float var = sq * (1.f / 200.f) - mu * mu;
                sm.p4.mu[w] = mu; sm.p4.is[w] = rsqrtf(var + 1e-3f);
            }
        }
        __syncthreads();
        if (t < 200) {
            float gg = gl1[t], be = bl1[t];
            long long s24 = 0, s20 = 0;
#pragma unroll
            for (int r = 0; r < 4; r++) {
                float v = (sm.p4.ys[r][t] - sm.p4.mu[r]) * sm.p4.is[r] * gg + be;
                g_y1[(size_t)t * BSZ + b0 + r] = v;
                s24 += llrintf(v * 16777216.f);            // 2^24 scale
                long long a20 = llrintf(v * 1048576.f);    // 2^20 scale
                s20 += a20 * a20;                          // v^2 * 2^40
            }
            atomicAdd(&g_s1sum[t], (unsigned long long)s24);
            atomicAdd(&g_s1sq[t],  (unsigned long long)s20);
        }
    }
    gbar();                                                   // barrier 2

    // ---------------- P6: stats from int sums + dice + MLP2 + LN -> y2T ------
    if (bid < 128) {
        int b0 = bid * 4;
        if (t < 200) {
            long long s = (long long)g_s1sum[t];
            long long q = (long long)g_s1sq[t];
            float mu = (float)s * (1.f / (512.f * 16777216.f));
            float ex2 = (float)q * (1.f / (512.f * 1099511627776.f));   // /2^40
            float is = rsqrtf(ex2 - mu * mu + 1e-3f);
            float a = al1[t];
            float4 v = *(const float4*)(g_y1 + (size_t)t * BSZ + b0);
            float p;
            p = sigm((v.x - mu) * is); sm.p6.d1s[t][0] = v.x * (p + a * (1.f - p));
            p = sigm((v.y - mu) * is); sm.p6.d1s[t][1] = v.y * (p + a * (1.f - p));
            p = sigm((v.z - mu) * is); sm.p6.d1s[t][2] = v.z * (p + a * (1.f - p));
            p = sigm((v.w - mu) * is); sm.p6.d1s[t][3] = v.w * (p + a * (1.f - p));
        }
        __syncthreads();

        if (t < 80) {
            float bb = bm2[t];
            float acc0 = bb, acc1 = bb, acc2 = bb, acc3 = bb;
            const float* wp = Wm2 + t;
#pragma unroll 8
            for (int j = 0; j < 200; j++) {
                float w = wp[j * 80];
                acc0 += w * sm.p6.d1s[j][0];
                acc1 += w * sm.p6.d1s[j][1];
                acc2 += w * sm.p6.d1s[j][2];
                acc3 += w * sm.p6.d1s[j][3];
            }
            sm.p6.ys[t][0] = acc0; sm.p6.ys[t][1] = acc1;
            sm.p6.ys[t][2] = acc2; sm.p6.ys[t][3] = acc3;
        }
        __syncthreads();
        if (t < 128) {
            int w = t >> 5, lane = t & 31;
            float smv = 0.f, sq = 0.f;
            for (int c = lane; c < 80; c += 32) { float v = sm.p6.ys[c][w]; smv += v; sq += v * v; }
#pragma unroll
            for (int o = 16; o; o >>= 1) {
                smv += __shfl_down_sync(0xffffffffu, smv, o);
                sq  += __shfl_down_sync(0xffffffffu, sq, o);
            }
            if (lane == 0) {
                float mu = smv * (1.f / 80.f);
                float var = sq * (1.f / 80.f) - mu * mu;
                sm.p6.mu[w] = mu; sm.p6.is[w] = rsqrtf(var + 1e-3f);
            }
        }
        __syncthreads();
        if (t < 80) {
            float gg = gl2[t], be = bl2[t];
#pragma unroll
            for (int r = 0; r < 4; r++)
                g_y2[(size_t)t * BSZ + b0 + r] =
                    (sm.p6.ys[t][r] - sm.p6.mu[r]) * sm.p6.is[r] * gg + be;
        }
    }
    gbar();                                                   // barrier 3

    // ---------------- P7: stats2 + dice + out GEMM + softmax ----------------
    if (bid < 32) {
        int w = t >> 5, lane = t & 31;
        int b0 = bid * 16;
        if (t < 160) sm.p7.Wsh[t] = Wo[t];
        if (t < 80) sm.p7.Ash[t] = al2[t];
        for (int r = 0; r < 10; r++) {
            int f = w * 10 + r;
            const float4* row = (const float4*)(g_y2 + (size_t)f * BSZ);
            float smv = 0.f, sq = 0.f;
#pragma unroll
            for (int i = 0; i < 4; i++) {
                float4 v = row[lane + 32 * i];
                smv += v.x + v.y + v.z + v.w;
                sq += v.x * v.x + v.y * v.y + v.z * v.z + v.w * v.w;
            }
#pragma unroll
            for (int o = 16; o; o >>= 1) {
                smv += __shfl_down_sync(0xffffffffu, smv, o);
                sq  += __shfl_down_sync(0xffffffffu, sq, o);
            }
            if (lane == 0) {
                float mu = smv * (1.f / 512.f);
                float var = sq * (1.f / 512.f) - mu * mu;
                sm.p7.mu2[f] = mu; sm.p7.is2[f] = rsqrtf(var + 1e-3f);
            }
        }
        __syncthreads();
        float bo0 = bo[0], bo1 = bo[1];
#pragma unroll
        for (int rep = 0; rep < 2; rep++) {
            int b = b0 + w + rep * 8;
            float a0 = 0.f, a1 = 0.f;
            for (int f = lane; f < 80; f += 32) {
                float v = g_y2[(size_t)f * BSZ + b];
                float xn = (v - sm.p7.mu2[f]) * sm.p7.is2[f];
                float p = sigm(xn);
                float h = v * (p + sm.p7.Ash[f] * (1.f - p));
                a0 += h * sm.p7.Wsh[2 * f];
                a1 += h * sm.p7.Wsh[2 * f + 1];
            }
#pragma unroll
            for (int o = 16; o; o >>= 1) {
                a0 += __shfl_down_sync(0xffffffffu, a0, o);
                a1 += __shfl_down_sync(0xffffffffu, a1, o);
            }
            if (lane == 0) {
                a0 += bo0; a1 += bo1;
                float m = fmaxf(a0, a1);
                float e0 = __expf(a0 - m), e1 = __expf(a1 - m);
                float inv = __fdividef(1.f, e0 + e1);
                out[b * 2] = e0 * inv;
                out[b * 2 + 1] = e1 * inv;
            }
        }
    }
}

// ============================================================================
extern "C" void kernel_launch(void* const* d_in, const int* in_sizes, int n_in,
                              void* d_out, int out_size) {
    (void)in_sizes; (void)n_in; (void)out_size;
    const int* uid  = (const int*)d_in[0];
    const int* ut1  = (const int*)d_in[1];
    const int* ut2  = (const int*)d_in[2];
    const int* ut3  = (const int*)d_in[3];
    const int* ut4  = (const int*)d_in[4];
    const int* ig   = (const int*)d_in[5];
    const int* ish  = (const int*)d_in[6];
    const int* ic   = (const int*)d_in[7];
    const int* vg   = (const int*)d_in[8];
    const int* vsh  = (const int*)d_in[9];
    const int* vc   = (const int*)d_in[10];
    const float* table     = (const float*)d_in[11];
    const float* W_act1    = (const float*)d_in[12];
    const float* b_act1    = (const float*)d_in[13];
    const float* alpha_act = (const float*)d_in[14];
    const float* W_act_out = (const float*)d_in[15];
    const float* b_act_out = (const float*)d_in[16];
    const float* W_mlp1    = (const float*)d_in[17];
    const float* b_mlp1    = (const float*)d_in[18];
    const float* g_ln1     = (const float*)d_in[19];
    const float* beta_ln1  = (const float*)d_in[20];
    const float* alpha_m1  = (const float*)d_in[21];
    const float* W_mlp2    = (const float*)d_in[22];
    const float* b_mlp2    = (const float*)d_in[23];
    const float* g_ln2     = (const float*)d_in[24];
    const float* beta_ln2  = (const float*)d_in[25];
    const float* alpha_m2  = (const float*)d_in[26];
    const float* W_out     = (const float*)d_in[27];
    const float* b_out     = (const float*)d_in[28];
    float* out = (float*)d_out;

    IdPtrs ids;
    ids.p[0] = uid; ids.p[1] = ut1; ids.p[2] = ut2; ids.p[3] = ut3;
    ids.p[4] = ut4; ids.p[5] = ig;  ids.p[6] = ish; ids.p[7] = ic;

    din_fused<<<NBLK, NTHR>>>(table, ids, vg, vsh, vc,
                              W_act1, b_act1, alpha_act, W_act_out, b_act_out,
                              W_mlp1, b_mlp1, g_ln1, beta_ln1, alpha_m1,
                              W_mlp2, b_mlp2, g_ln2, beta_ln2, alpha_m2,
                              W_out, b_out, out);
}